// round 8
// baseline (speedup 1.0000x reference)
#include <cuda_runtime.h>
#include <cstdint>

// InferenceEmbeddingTable: hash-bucket lookup + embedding row gather.
// R6: IPW=8, lane-specialized metadata (lanes 0..7 own one index each:
// key, table resolve, bucket hash, predicted slot k/nb, 4B verify load).
// 8 speculative 512B gathers in flight per warp before any store;
// stores are UNCONDITIONAL (speculative), the cold fallback overwrites
// any unverified index afterward (same-thread program order wins).
// __launch_bounds__(128,9) pins regs <=56 so 36 warps/SM stay resident.

#define BUCKET_CAP 128
#define IPW 8                      // indices per warp

__global__ __launch_bounds__(128, 9)
void emb_lookup_kernel(const int* __restrict__ indices,
                       const int* __restrict__ offsets,
                       const int* __restrict__ bucket_keys,    // [total_buckets*128]
                       const int* __restrict__ table_offsets,
                       const int* __restrict__ table_bucket_offsets,
                       const int* __restrict__ num_buckets,
                       const float4* __restrict__ emb,         // [total_rows*32]
                       float4* __restrict__ out,               // [N*32]
                       int N, int num_features)
{
    const int gtid = blockIdx.x * blockDim.x + threadIdx.x;
    const int warp = gtid >> 5;
    const int lane = threadIdx.x & 31;
    const int base = warp * IPW;
    if (base >= N) return;

    // ---- lanes 0..7: per-index metadata as scalars -------------------------
    int key = 0, row = 0, bg = 0, tj = 0, bl = 0, chk = (int)0x80000000;
    bool valid = false;
    if (lane < IPW) {
        const int pos = base + lane;
        key = (pos < N) ? __ldg(&indices[pos]) : 0;
        int t = 0;
        for (int f = 1; f < num_features; ++f)
            t += (pos >= __ldg(&offsets[f]));
        tj = t;
        const unsigned nb = (unsigned)__ldg(&num_buckets[t]);
        unsigned b, g;
        if ((nb & (nb - 1u)) == 0u) {                 // pow2 fast path
            b = (unsigned)key & (nb - 1u);
            g = (unsigned)key >> __popc(nb - 1u);
        } else {
            b = (unsigned)key % nb;
            g = (unsigned)key / nb;
        }
        bl    = (int)b;
        valid = (g < BUCKET_CAP);
        const int gs = valid ? (int)g : 0;
        bg    = __ldg(&table_bucket_offsets[t]) + (int)b;
        row   = __ldg(&table_offsets[t]) + (int)b * BUCKET_CAP + gs;
        chk   = __ldg(&bucket_keys[bg * BUCKET_CAP + gs]);   // verify (L2)
    }

    // ---- broadcast rows, launch 8 speculative gathers (DRAM, MLP=8) -------
    int r[IPW];
    #pragma unroll
    for (int j = 0; j < IPW; ++j)
        r[j] = __shfl_sync(0xffffffffu, row, j);

    float4 v[IPW];
    #pragma unroll
    for (int j = 0; j < IPW; ++j)
        v[j] = __ldcs(&emb[r[j] * 32 + lane]);

    // ---- unconditional speculative stores (verify off the critical path) --
    #pragma unroll
    for (int j = 0; j < IPW; ++j) {
        const int pos = base + j;
        if (pos < N) __stcs(&out[pos * 32 + lane], v[j]);
    }

    // ---- verification ballot; cold fallback overwrites bad rows -----------
    const unsigned okm = __ballot_sync(0xffffffffu,
                                       (lane < IPW) && valid && (chk == key));
    if (__builtin_expect((okm & 0xffu) != 0xffu, 0)) {
        #pragma unroll
        for (int j = 0; j < IPW; ++j) {
            const int pos = base + j;
            if (pos >= N) break;
            if ((okm >> j) & 1u) continue;
            const int kj  = __shfl_sync(0xffffffffu, key, j);
            const int bgj = __shfl_sync(0xffffffffu, bg,  j);
            const int tjj = __shfl_sync(0xffffffffu, tj,  j);
            const int blj = __shfl_sync(0xffffffffu, bl,  j);
            const int4 kk = __ldg((const int4*)bucket_keys + bgj * 32 + lane);
            const int m = (kk.x == kj ? 1 : 0) | (kk.y == kj ? 2 : 0)
                        | (kk.z == kj ? 4 : 0) | (kk.w == kj ? 8 : 0);
            const int cand = m ? (lane * 4 + (__ffs(m) - 1)) : 0x7fffffff;
            const int slot = __reduce_min_sync(0xffffffffu, cand);
            float4 rr = make_float4(0.f, 0.f, 0.f, 0.f);
            if (slot < BUCKET_CAP) {
                const int row2 = __ldg(&table_offsets[tjj]) + blj * BUCKET_CAP + slot;
                rr = __ldcs(&emb[row2 * 32 + lane]);
            }
            __stcs(&out[pos * 32 + lane], rr);   // same thread, later in program
        }                                        // order -> overwrites speculation
    }
}

extern "C" void kernel_launch(void* const* d_in, const int* in_sizes, int n_in,
                              void* d_out, int out_size)
{
    const int*    indices              = (const int*)   d_in[0];
    const int*    offsets              = (const int*)   d_in[1];
    const int*    bucket_keys          = (const int*)   d_in[2];
    const int*    table_offsets        = (const int*)   d_in[3];
    const int*    table_bucket_offsets = (const int*)   d_in[4];
    const int*    num_buckets          = (const int*)   d_in[5];
    const float4* emb                  = (const float4*)d_in[6];
    float4*       out                  = (float4*)      d_out;

    const int N            = in_sizes[0];
    const int num_features = in_sizes[5];

    const int threads = 128;                       // 4 warps * 8 idx = 32 idx/block
    const int idx_per_block = (threads / 32) * IPW;
    const int blocks = (N + idx_per_block - 1) / idx_per_block;

    emb_lookup_kernel<<<blocks, threads>>>(indices, offsets, bucket_keys,
                                           table_offsets, table_bucket_offsets,
                                           num_buckets, emb, out,
                                           N, num_features);
}

// round 9
// speedup vs baseline: 1.0133x; 1.0133x over previous
#include <cuda_runtime.h>
#include <cstdint>

// InferenceEmbeddingTable: hash-bucket lookup + embedding row gather.
// R7 = R5 (best config: IPW=4, 256 thr, regs~32, occ~84%) + unconditional
// speculative stores (store no longer depends on the verification ballot;
// the correct-for-arbitrary-data fallback overwrites any mismatch after,
// same-thread program order guarantees the final value).

#define BUCKET_CAP 128
#define IPW 4                      // indices per warp

__global__ __launch_bounds__(256)
void emb_lookup_kernel(const int* __restrict__ indices,
                       const int* __restrict__ offsets,
                       const int* __restrict__ bucket_keys,    // [total_buckets*128]
                       const int* __restrict__ table_offsets,
                       const int* __restrict__ table_bucket_offsets,
                       const int* __restrict__ num_buckets,
                       const float4* __restrict__ emb,         // [total_rows*32]
                       float4* __restrict__ out,               // [N*32]
                       int N, int num_features)
{
    const int gtid = blockIdx.x * blockDim.x + threadIdx.x;
    const int warp = gtid >> 5;
    const int lane = threadIdx.x & 31;
    const int base = warp * IPW;
    if (base >= N) return;

    // ---- lanes 0..3: per-index metadata as scalars -------------------------
    int key = 0, row = 0, bg = 0, tj = 0, bl = 0, chk = (int)0x80000000;
    bool valid = false;
    if (lane < IPW) {
        const int pos = base + lane;
        key = (pos < N) ? __ldg(&indices[pos]) : 0;
        int t = 0;
        for (int f = 1; f < num_features; ++f)
            t += (pos >= __ldg(&offsets[f]));
        tj = t;
        const unsigned nb = (unsigned)__ldg(&num_buckets[t]);
        unsigned b, g;
        if ((nb & (nb - 1u)) == 0u) {                 // pow2 fast path
            b = (unsigned)key & (nb - 1u);
            g = (unsigned)key >> __popc(nb - 1u);
        } else {
            b = (unsigned)key % nb;
            g = (unsigned)key / nb;
        }
        bl    = (int)b;
        valid = (g < BUCKET_CAP);
        const int gs = valid ? (int)g : 0;
        bg    = __ldg(&table_bucket_offsets[t]) + (int)b;
        row   = __ldg(&table_offsets[t]) + (int)b * BUCKET_CAP + gs;
        chk   = __ldg(&bucket_keys[bg * BUCKET_CAP + gs]);   // verify (L2)
    }

    // ---- broadcast rows, launch 4 speculative gathers (DRAM, MLP=4) -------
    const int r0 = __shfl_sync(0xffffffffu, row, 0);
    const int r1 = __shfl_sync(0xffffffffu, row, 1);
    const int r2 = __shfl_sync(0xffffffffu, row, 2);
    const int r3 = __shfl_sync(0xffffffffu, row, 3);
    const float4 v0 = __ldcs(&emb[r0 * 32 + lane]);
    const float4 v1 = __ldcs(&emb[r1 * 32 + lane]);
    const float4 v2 = __ldcs(&emb[r2 * 32 + lane]);
    const float4 v3 = __ldcs(&emb[r3 * 32 + lane]);

    // ---- unconditional speculative stores (no ballot on the store path) ---
    if (base + 0 < N) __stcs(&out[(base + 0) * 32 + lane], v0);
    if (base + 1 < N) __stcs(&out[(base + 1) * 32 + lane], v1);
    if (base + 2 < N) __stcs(&out[(base + 2) * 32 + lane], v2);
    if (base + 3 < N) __stcs(&out[(base + 3) * 32 + lane], v3);

    // ---- verification ballot; cold fallback overwrites bad rows -----------
    const unsigned okm = __ballot_sync(0xffffffffu,
                                       (lane < IPW) && valid && (chk == key));
    if (__builtin_expect((okm & 0xfu) != 0xfu, 0)) {
        #pragma unroll
        for (int j = 0; j < IPW; ++j) {
            const int pos = base + j;
            if (pos >= N) break;
            if ((okm >> j) & 1u) continue;
            const int kj  = __shfl_sync(0xffffffffu, key, j);
            const int bgj = __shfl_sync(0xffffffffu, bg,  j);
            const int tjj = __shfl_sync(0xffffffffu, tj,  j);
            const int blj = __shfl_sync(0xffffffffu, bl,  j);
            const int4 kk = __ldg((const int4*)bucket_keys + bgj * 32 + lane);
            const int m = (kk.x == kj ? 1 : 0) | (kk.y == kj ? 2 : 0)
                        | (kk.z == kj ? 4 : 0) | (kk.w == kj ? 8 : 0);
            const int cand = m ? (lane * 4 + (__ffs(m) - 1)) : 0x7fffffff;
            const int slot = __reduce_min_sync(0xffffffffu, cand);
            float4 rr = make_float4(0.f, 0.f, 0.f, 0.f);
            if (slot < BUCKET_CAP) {
                const int row2 = __ldg(&table_offsets[tjj]) + blj * BUCKET_CAP + slot;
                rr = __ldcs(&emb[row2 * 32 + lane]);
            }
            __stcs(&out[pos * 32 + lane], rr);   // later in program order:
        }                                        // overwrites the speculation
    }
}

extern "C" void kernel_launch(void* const* d_in, const int* in_sizes, int n_in,
                              void* d_out, int out_size)
{
    const int*    indices              = (const int*)   d_in[0];
    const int*    offsets              = (const int*)   d_in[1];
    const int*    bucket_keys          = (const int*)   d_in[2];
    const int*    table_offsets        = (const int*)   d_in[3];
    const int*    table_bucket_offsets = (const int*)   d_in[4];
    const int*    num_buckets          = (const int*)   d_in[5];
    const float4* emb                  = (const float4*)d_in[6];
    float4*       out                  = (float4*)      d_out;

    const int N            = in_sizes[0];
    const int num_features = in_sizes[5];

    const int threads = 256;                       // 8 warps * 4 idx = 32 idx/block
    const int idx_per_block = (threads / 32) * IPW;
    const int blocks = (N + idx_per_block - 1) / idx_per_block;

    emb_lookup_kernel<<<blocks, threads>>>(indices, offsets, bucket_keys,
                                           table_offsets, table_bucket_offsets,
                                           num_buckets, emb, out,
                                           N, num_features);
}